// round 1
// baseline (speedup 1.0000x reference)
#include <cuda_runtime.h>
#include <cuda_bf16.h>
#include <cstdint>

#define IN_FEAT   256
#define OUT_FEAT  32
#define MAX_NODES 100000

// Scratch for projected features x = feat @ W   (12.8 MB)
__device__ float g_x[MAX_NODES * OUT_FEAT];

// ---------------------------------------------------------------------------
// Stage 1: x = feat @ W
// One thread per node-row; 32 output cols as 16 packed f32x2 accumulators.
// W staged in shared (32 KB); per k: 1 scalar a (from a float4 register),
// 8 broadcast LDS.128 of W row, 16 fma.rn.f32x2.
// ---------------------------------------------------------------------------
__device__ __forceinline__ void ffma2(unsigned long long& acc,
                                      unsigned long long a,
                                      unsigned long long b) {
    asm("fma.rn.f32x2 %0, %1, %2, %0;" : "+l"(acc) : "l"(a), "l"(b));
}

__device__ __forceinline__ unsigned long long pack_dup(float a) {
    unsigned long long r;
    asm("mov.b64 %0, {%1, %1};" : "=l"(r) : "f"(a));
    return r;
}

__global__ __launch_bounds__(256, 3)
void gemm_kernel(const float* __restrict__ feat,
                 const float* __restrict__ weight,
                 int n_nodes) {
    __shared__ float sW[IN_FEAT * OUT_FEAT];  // 32 KB, layout identical to global

    // cooperative coalesced load of W
    const float4* wg4 = (const float4*)weight;
    float4* sw4 = (float4*)sW;
    #pragma unroll
    for (int i = threadIdx.x; i < (IN_FEAT * OUT_FEAT) / 4; i += 256)
        sw4[i] = wg4[i];
    __syncthreads();

    int row = blockIdx.x * 256 + threadIdx.x;
    if (row >= n_nodes) return;

    const float4* fr = (const float4*)(feat + (size_t)row * IN_FEAT);

    unsigned long long acc[16];
    #pragma unroll
    for (int i = 0; i < 16; i++) acc[i] = 0ull;

    #pragma unroll 2
    for (int kk = 0; kk < IN_FEAT / 4; kk++) {
        float4 a4 = __ldg(fr + kk);
        float av[4] = {a4.x, a4.y, a4.z, a4.w};
        #pragma unroll
        for (int s = 0; s < 4; s++) {
            int k = kk * 4 + s;
            unsigned long long aa = pack_dup(av[s]);
            const ulonglong2* wrow = (const ulonglong2*)(sW + k * OUT_FEAT);
            #pragma unroll
            for (int i = 0; i < 8; i++) {
                ulonglong2 b = wrow[i];       // cols 4i..4i+3, broadcast LDS.128
                ffma2(acc[2 * i],     aa, b.x);
                ffma2(acc[2 * i + 1], aa, b.y);
            }
        }
    }

    // write 32 floats (8 x STG.128)
    float4* xo = (float4*)(g_x + (size_t)row * OUT_FEAT);
    #pragma unroll
    for (int i = 0; i < 8; i++) {
        float2 lo = *(float2*)&acc[2 * i];
        float2 hi = *(float2*)&acc[2 * i + 1];
        float4 v;
        v.x = lo.x; v.y = lo.y; v.z = hi.x; v.w = hi.y;
        xo[i] = v;
    }
}

// ---------------------------------------------------------------------------
// Stage 2: out[row[e]] += vals[e] * x[col[e]]
// 8 threads per edge, float4 gather + red.global.add.v4.f32 scatter
// (4x fewer reduction ops than scalar atomicAdd).
// ---------------------------------------------------------------------------
__global__ __launch_bounds__(256)
void spmm_kernel(const float* __restrict__ vals,
                 const int* __restrict__ erow,
                 const int* __restrict__ ecol,
                 float* __restrict__ out,
                 int n_edges) {
    int idx = blockIdx.x * 256 + threadIdx.x;
    int e = idx >> 3;
    if (e >= n_edges) return;
    int q = (idx & 7) << 2;  // float offset within the 32-wide row

    int   c = __ldg(ecol + e);
    int   r = __ldg(erow + e);
    float v = __ldg(vals + e);

    float4 xv = *(const float4*)(g_x + c * OUT_FEAT + q);
    float4 m;
    m.x = v * xv.x; m.y = v * xv.y; m.z = v * xv.z; m.w = v * xv.w;

    float* dst = out + r * OUT_FEAT + q;
    asm volatile("red.global.add.v4.f32 [%0], {%1, %2, %3, %4};"
                 :: "l"(dst), "f"(m.x), "f"(m.y), "f"(m.z), "f"(m.w)
                 : "memory");
}

// ---------------------------------------------------------------------------
extern "C" void kernel_launch(void* const* d_in, const int* in_sizes, int n_in,
                              void* d_out, int out_size) {
    const float* feat   = (const float*)d_in[0];
    const float* weight = (const float*)d_in[1];
    const float* vals   = (const float*)d_in[2];
    const int*   erow   = (const int*)d_in[3];
    const int*   ecol   = (const int*)d_in[4];
    float* out = (float*)d_out;

    int n_nodes = in_sizes[0] / IN_FEAT;
    int n_edges = in_sizes[2];

    // zero-init output (d_out is poisoned)
    cudaMemsetAsync(out, 0, (size_t)out_size * sizeof(float), 0);

    int gemm_blocks = (n_nodes + 255) / 256;
    gemm_kernel<<<gemm_blocks, 256>>>(feat, weight, n_nodes);

    long long work = (long long)n_edges * 8;
    int spmm_blocks = (int)((work + 255) / 256);
    spmm_kernel<<<spmm_blocks, 256>>>(vals, erow, ecol, out, n_edges);
}